// round 9
// baseline (speedup 1.0000x reference)
#include <cuda_runtime.h>
#include <cuda_fp16.h>
#include <cstdint>

#define N_TOK 2304
#define BATCH 4
#define HEADS 8
#define DHEAD 32
#define HIDDEN 256
#define QSCALE 0.17677669529663689f  // 32^-0.5

// ---- tf32 helpers (projection GEMMs) ----
__device__ __forceinline__ uint32_t cvt_tf32(float f) {
    uint32_t r; asm("cvt.rna.tf32.f32 %0,%1;" : "=r"(r) : "f"(f)); return r;
}
__device__ __forceinline__ void mma_tf32(float c[4], const uint32_t a[4],
                                         uint32_t b0, uint32_t b1) {
    asm("mma.sync.aligned.m16n8k8.row.col.f32.tf32.tf32.f32 "
        "{%0,%1,%2,%3},{%4,%5,%6,%7},{%8,%9},{%0,%1,%2,%3};"
        : "+f"(c[0]), "+f"(c[1]), "+f"(c[2]), "+f"(c[3])
        : "r"(a[0]), "r"(a[1]), "r"(a[2]), "r"(a[3]), "r"(b0), "r"(b1));
}

// ---- fp16 helpers (attention) ----
__device__ __forceinline__ uint32_t h2pk(float lo, float hi) {
    uint32_t r; asm("cvt.rn.f16x2.f32 %0,%1,%2;" : "=r"(r) : "f"(hi), "f"(lo)); return r;
}
__device__ __forceinline__ void mma_f16(float c[4], const uint32_t a[4],
                                        uint32_t b0, uint32_t b1) {
    asm("mma.sync.aligned.m16n8k16.row.col.f32.f16.f16.f32 "
        "{%0,%1,%2,%3},{%4,%5,%6,%7},{%8,%9},{%0,%1,%2,%3};"
        : "+f"(c[0]), "+f"(c[1]), "+f"(c[2]), "+f"(c[3])
        : "r"(a[0]), "r"(a[1]), "r"(a[2]), "r"(a[3]), "r"(b0), "r"(b1));
}
__device__ __forceinline__ void ldmx4t(uint32_t r[4], uint32_t addr) {
    asm volatile("ldmatrix.sync.aligned.m8n8.x4.trans.shared.b16 {%0,%1,%2,%3},[%4];"
                 : "=r"(r[0]), "=r"(r[1]), "=r"(r[2]), "=r"(r[3]) : "r"(addr));
}

// ---- cp.async helpers ----
__device__ __forceinline__ void cpa16(uint32_t smem_dst, const void* gsrc) {
    asm volatile("cp.async.cg.shared.global [%0],[%1],16;" :: "r"(smem_dst), "l"(gsrc));
}
__device__ __forceinline__ void cpa_commit() { asm volatile("cp.async.commit_group;"); }
__device__ __forceinline__ void cpa_wait0()  { asm volatile("cp.async.wait_group 0;"); }

// Scratch (alloc-free rule: __device__ globals)
__device__ __half g_qkvh[BATCH * 3 * HIDDEN * N_TOK];   // fp16 qkv
__device__ float  g_ao  [BATCH * HIDDEN * N_TOK];       // f32 attn out

// ---------------------------------------------------------------------------
// tf32 GEMM, double-buffered staging (1 barrier per 32k chunk).
// ---------------------------------------------------------------------------
#define GPX 136

__global__ __launch_bounds__(256)
void gemm_tf32(const float* __restrict__ W, const float* __restrict__ X,
               void* __restrict__ Yv, int M,
               const float* __restrict__ bias, int qscale, int out_half)
{
    __shared__ uint32_t sX[2][32 * GPX];

    const int b  = blockIdx.z;
    const int m0 = blockIdx.y * 128;
    const int j0 = blockIdx.x * 128;
    const int tid = threadIdx.x;
    const int lane = tid & 31, warp = tid >> 5;
    const int g = lane >> 2, tg = lane & 3;
    const int mw = m0 + 16 * warp;

    const float* Xb = X + (size_t)b * 256 * N_TOK;

    // per-thread staging coordinates (4 float4 slots)
    int skk[4], sj4[4];
#pragma unroll
    for (int l = 0; l < 4; l++) {
        int t = tid + l * 256;
        skk[l] = t >> 5; sj4[l] = (t & 31) << 2;
    }

    float acc[16][4];
#pragma unroll
    for (int nt = 0; nt < 16; nt++)
#pragma unroll
        for (int c = 0; c < 4; c++) acc[nt][c] = 0.f;

    float4 xr[4];
    // prologue: chunk 0
#pragma unroll
    for (int l = 0; l < 4; l++)
        xr[l] = *(const float4*)(Xb + (size_t)skk[l] * N_TOK + j0 + sj4[l]);
#pragma unroll
    for (int l = 0; l < 4; l++) {
        uint4 xu = { cvt_tf32(xr[l].x), cvt_tf32(xr[l].y), cvt_tf32(xr[l].z), cvt_tf32(xr[l].w) };
        *(uint4*)&sX[0][skk[l] * GPX + sj4[l]] = xu;
    }

    for (int c = 0; c < 8; c++) {
        __syncthreads();
        const int k0 = c * 32;
        if (c < 7) {
#pragma unroll
            for (int l = 0; l < 4; l++)
                xr[l] = *(const float4*)(Xb + (size_t)(k0 + 32 + skk[l]) * N_TOK + j0 + sj4[l]);
        }
        const uint32_t* sXc = sX[c & 1];
#pragma unroll
        for (int kc = 0; kc < 4; kc++) {
            const float* wr = W + (size_t)(mw + g) * 256 + k0 + kc * 8 + tg;
            uint32_t a[4];
            a[0] = cvt_tf32(wr[0]);
            a[1] = cvt_tf32(wr[8 * 256]);
            a[2] = cvt_tf32(wr[4]);
            a[3] = cvt_tf32(wr[8 * 256 + 4]);
#pragma unroll
            for (int nt = 0; nt < 16; nt++) {
                uint32_t b0 = sXc[(kc * 8 + tg)     * GPX + nt * 8 + g];
                uint32_t b1 = sXc[(kc * 8 + tg + 4) * GPX + nt * 8 + g];
                mma_tf32(acc[nt], a, b0, b1);
            }
        }
        if (c < 7) {
            uint32_t* sXn = sX[(c + 1) & 1];
#pragma unroll
            for (int l = 0; l < 4; l++) {
                uint4 xu = { cvt_tf32(xr[l].x), cvt_tf32(xr[l].y), cvt_tf32(xr[l].z), cvt_tf32(xr[l].w) };
                *(uint4*)&sXn[skk[l] * GPX + sj4[l]] = xu;
            }
        }
    }

    const int mr0 = mw + g, mr1 = mw + g + 8;
    const float s0 = (qscale && mr0 < HIDDEN) ? QSCALE : 1.f;
    const float s1 = (qscale && mr1 < HIDDEN) ? QSCALE : 1.f;
    if (out_half) {
        __half* Yh = (__half*)Yv;
        __half* y0 = Yh + ((size_t)b * M + mr0) * N_TOK + j0 + 2 * tg;
        __half* y1 = Yh + ((size_t)b * M + mr1) * N_TOK + j0 + 2 * tg;
#pragma unroll
        for (int nt = 0; nt < 16; nt++) {
            *(uint32_t*)(y0 + nt * 8) = h2pk(acc[nt][0] * s0, acc[nt][1] * s0);
            *(uint32_t*)(y1 + nt * 8) = h2pk(acc[nt][2] * s1, acc[nt][3] * s1);
        }
    } else {
        float* Yf = (float*)Yv;
        const float bv0 = bias ? bias[mr0] : 0.f;
        const float bv1 = bias ? bias[mr1] : 0.f;
        float* y0 = Yf + ((size_t)b * M + mr0) * N_TOK + j0 + 2 * tg;
        float* y1 = Yf + ((size_t)b * M + mr1) * N_TOK + j0 + 2 * tg;
#pragma unroll
        for (int nt = 0; nt < 16; nt++) {
            float2 o0 = { fmaf(acc[nt][0], s0, bv0), fmaf(acc[nt][1], s0, bv0) };
            float2 o1 = { fmaf(acc[nt][2], s1, bv1), fmaf(acc[nt][3], s1, bv1) };
            *(float2*)(y0 + nt * 8) = o0;
            *(float2*)(y1 + nt * 8) = o1;
        }
    }
}

// ---------------------------------------------------------------------------
// Batch-fused flash attention, fully double-buffered:
//  - K/V fp16 x2 buffers via cp.async, prefetched one full tile ahead
//  - pos_bias fp16 x2 buffers via LDG->pack->STS interleaved into compute
// One barrier per tile. Max-free softmax, fp16 mma, register-resident P.
// ---------------------------------------------------------------------------
#define HP 136                           // halves per d-row
#define KV_PB (2 * 32 * HP)              // per-batch K+V halves (8704)
#define KVBUF_H (BATCH * KV_PB)          // halves per K/V buffer (34816)
#define BIAS_H (128 * HP)                // halves per bias buffer (17408)
#define OFF_BIAS (2 * KVBUF_H)           // 69632 (halves)
#define ATTN_SMEM ((OFF_BIAS + 2 * BIAS_H) * 2)   // 208896 bytes
#define NTILES (N_TOK / 128)

__global__ __launch_bounds__(512, 1)
void attn_mma(const __half* __restrict__ qkvh, const float* __restrict__ posb,
              float* __restrict__ ao)
{
    extern __shared__ __align__(16) uint16_t sH[];

    const int h = blockIdx.y, i0 = blockIdx.x * 128;
    const int tid  = threadIdx.x;
    const int lane = tid & 31, warp = tid >> 5;
    const int bb = warp & 3, mt = warp >> 2;
    const int g = lane >> 2, tg = lane & 3;

    const uint32_t smem_u32 = (uint32_t)__cvta_generic_to_shared(sH);

    const uint16_t* qh = (const uint16_t*)(qkvh + ((size_t)bb * 3 * HIDDEN + h * DHEAD) * N_TOK);
    const float* pbase = posb + (size_t)h * N_TOK * N_TOK;

    const int gi0 = i0 + 32 * mt + g;

    // per-thread K/V staging slots (8 cpa16 each tile)
    int kv_half[8]; const __half* kv_src_base[8];
#pragma unroll
    for (int l = 0; l < 8; l++) {
        int t = tid + l * 512;
        int isv = t >> 11, t2 = t & 2047;
        int bbs = t2 >> 9, r = t2 & 511;
        int d = r >> 4, ch = r & 15;
        kv_half[l] = bbs * KV_PB + isv * 32 * HP + d * HP + ch * 8;
        kv_src_base[l] = qkvh
            + ((size_t)(bbs * 3 * HIDDEN + (1 + isv) * HIDDEN + h * DHEAD + d)) * N_TOK + ch * 8;
    }

    // Q A-fragments fp16, held all kernel
    uint32_t qa[2][2][4];
#pragma unroll
    for (int rt = 0; rt < 2; rt++) {
        const int gi = gi0 + 16 * rt;
#pragma unroll
        for (int kc = 0; kc < 2; kc++) {
            int d0 = kc * 16 + 2 * tg;
#pragma unroll
            for (int q = 0; q < 4; q++) {
                int dd = d0 + (q >> 1) * 8;
                int ii = gi + (q & 1) * 8;
                qa[rt][kc][q] = (uint32_t)qh[(size_t)dd * N_TOK + ii]
                              | ((uint32_t)qh[(size_t)(dd + 1) * N_TOK + ii] << 16);
            }
        }
    }

    float o[2][4][4];
#pragma unroll
    for (int rt = 0; rt < 2; rt++)
#pragma unroll
        for (int dn = 0; dn < 4; dn++)
#pragma unroll
            for (int c = 0; c < 4; c++) o[rt][dn][c] = 0.f;
    float lp[2][2] = {{0.f,0.f},{0.f,0.f}};

    // ---- prologue: K/V tile 0 (cp.async) + bias tile 0 (LDG->STS fp16) ----
#pragma unroll
    for (int l = 0; l < 8; l++)
        cpa16(smem_u32 + (uint32_t)kv_half[l] * 2, kv_src_base[l]);
    cpa_commit();
    {
        __half* sB0 = (__half*)(sH + OFF_BIAS);
#pragma unroll
        for (int l = 0; l < 8; l++) {
            int s = tid + l * 512;
            int row = s >> 5, c4 = (s & 31) << 2;
            float4 v = *(const float4*)(pbase + (size_t)(i0 + row) * N_TOK + c4);
            *(uint2*)&sB0[row * HP + c4] = make_uint2(h2pk(v.x, v.y), h2pk(v.z, v.w));
        }
    }

    for (int jt = 0; jt < NTILES; jt++) {
        cpa_wait0();
        __syncthreads();

        const int cur = jt & 1, nxt = cur ^ 1;
        const bool pre = (jt + 1 < NTILES);

        if (pre) {   // prefetch K/V for next tile into other buffer
            const int jn = (jt + 1) * 128;
#pragma unroll
            for (int l = 0; l < 8; l++)
                cpa16(smem_u32 + (uint32_t)(nxt * KVBUF_H + kv_half[l]) * 2,
                      kv_src_base[l] + jn);
            cpa_commit();
        }

        const __half* sB = (const __half*)(sH + OFF_BIAS + cur * BIAS_H);
        __half* sBn = (__half*)(sH + OFF_BIAS + nxt * BIAS_H);
        const uint16_t* sVh = sH + cur * KVBUF_H + bb * KV_PB + 32 * HP;
        const uint32_t kaddr0 = smem_u32 + (uint32_t)(cur * KVBUF_H + bb * KV_PB) * 2
                              + (uint32_t)lane * (HP * 2);
        const float* pnext = pbase + (size_t)i0 * N_TOK + (jt + 1) * 128;

        float4 pend[2];
#pragma unroll
        for (int ntp = 0; ntp < 8; ntp++) {
            // interleaved bias_{t+1} staging: store slot ntp-2, load slot ntp
            if (pre && ntp >= 2) {
                int s = (ntp - 2) * 512 + tid;
                int row = s >> 5, c4 = (s & 31) << 2;
                float4 v = pend[ntp & 1];
                *(uint2*)&sBn[row * HP + c4] = make_uint2(h2pk(v.x, v.y), h2pk(v.z, v.w));
            }
            if (pre) {
                int s = ntp * 512 + tid;
                int row = s >> 5, c4 = (s & 31) << 2;
                pend[ntp & 1] = *(const float4*)(pnext + (size_t)row * N_TOK + c4);
            }

            uint32_t pa[2][4];
#pragma unroll
            for (int half = 0; half < 2; half++) {
                const int nt = 2 * ntp + half;
                uint32_t kf[4];
                ldmx4t(kf, kaddr0 + (uint32_t)nt * 16);
#pragma unroll
                for (int rt = 0; rt < 2; rt++) {
                    const int row0 = 32 * mt + 16 * rt + g;
                    __half2 b0h = *(const __half2*)&sB[row0 * HP + nt * 8 + 2 * tg];
                    __half2 b1h = *(const __half2*)&sB[(row0 + 8) * HP + nt * 8 + 2 * tg];
                    float2 x0 = __half22float2(b0h);
                    float2 x1 = __half22float2(b1h);
                    float c[4] = { x0.x, x0.y, x1.x, x1.y };
                    mma_f16(c, qa[rt][0], kf[0], kf[1]);
                    mma_f16(c, qa[rt][1], kf[2], kf[3]);
                    float e0 = __expf(c[0]), e1 = __expf(c[1]);
                    float e2 = __expf(c[2]), e3 = __expf(c[3]);
                    lp[rt][0] += e0 + e1;
                    lp[rt][1] += e2 + e3;
                    pa[rt][2 * half]     = h2pk(e0, e1);
                    pa[rt][2 * half + 1] = h2pk(e2, e3);
                }
            }
#pragma unroll
            for (int dn = 0; dn < 4; dn++) {
                uint32_t b0 = *(const uint32_t*)&sVh[(dn * 8 + g) * HP + ntp * 16 + 2 * tg];
                uint32_t b1 = *(const uint32_t*)&sVh[(dn * 8 + g) * HP + ntp * 16 + 8 + 2 * tg];
                mma_f16(o[0][dn], pa[0], b0, b1);
                mma_f16(o[1][dn], pa[1], b0, b1);
            }
        }
        if (pre) {   // flush bias slots 6,7
#pragma unroll
            for (int l = 6; l < 8; l++) {
                int s = l * 512 + tid;
                int row = s >> 5, c4 = (s & 31) << 2;
                float4 v = pend[l & 1];
                *(uint2*)&sBn[row * HP + c4] = make_uint2(h2pk(v.x, v.y), h2pk(v.z, v.w));
            }
        }
    }

    // ---- epilogue: reduce l across quad lanes, normalize, stage, store ----
    float* sO = (float*)sH;   // [batch][128][33] f32 = 67584 B (buffer 0 region only)
#pragma unroll
    for (int rt = 0; rt < 2; rt++) {
        float l0 = lp[rt][0], l1 = lp[rt][1];
        l0 += __shfl_xor_sync(0xffffffffu, l0, 1);
        l0 += __shfl_xor_sync(0xffffffffu, l0, 2);
        l1 += __shfl_xor_sync(0xffffffffu, l1, 1);
        l1 += __shfl_xor_sync(0xffffffffu, l1, 2);
        float inv0 = 1.f / l0, inv1 = 1.f / l1;
        int row0 = 32 * mt + 16 * rt + g;
        float* sOb = sO + bb * (128 * 33);
#pragma unroll
        for (int dn = 0; dn < 4; dn++) {
            int dcol = dn * 8 + 2 * tg;
            sOb[row0       * 33 + dcol]     = o[rt][dn][0] * inv0;
            sOb[row0       * 33 + dcol + 1] = o[rt][dn][1] * inv0;
            sOb[(row0 + 8) * 33 + dcol]     = o[rt][dn][2] * inv1;
            sOb[(row0 + 8) * 33 + dcol + 1] = o[rt][dn][3] * inv1;
        }
    }
    __syncthreads();
#pragma unroll
    for (int t = tid; t < 16384; t += 512) {
        int bbs = t >> 12, r = t & 4095;
        int d = r >> 7, ii = r & 127;
        ao[((size_t)bbs * HIDDEN + h * DHEAD + d) * N_TOK + i0 + ii] =
            sO[bbs * (128 * 33) + ii * 33 + d];
    }
}

// ---------------------------------------------------------------------------
extern "C" void kernel_launch(void* const* d_in, const int* in_sizes, int n_in,
                              void* d_out, int out_size)
{
    const float* x        = (const float*)d_in[0];
    const float* pos_bias = (const float*)d_in[1];
    const float* w_qkv    = (const float*)d_in[2];
    const float* w_out    = (const float*)d_in[3];
    const float* b_out    = (const float*)d_in[4];
    float* out = (float*)d_out;

    __half* qkvh_ptr; float* ao_ptr;
    cudaGetSymbolAddress((void**)&qkvh_ptr, g_qkvh);
    cudaGetSymbolAddress((void**)&ao_ptr,  g_ao);

    cudaFuncSetAttribute(attn_mma, cudaFuncAttributeMaxDynamicSharedMemorySize, ATTN_SMEM);

    dim3 gA(N_TOK / 128, (3 * HIDDEN) / 128, BATCH);
    gemm_tf32<<<gA, dim3(256)>>>(w_qkv, x, qkvh_ptr, 3 * HIDDEN, nullptr, 1, 1);

    dim3 gB(N_TOK / 128, HEADS);
    attn_mma<<<gB, dim3(512), ATTN_SMEM>>>(qkvh_ptr, pos_bias, ao_ptr);

    dim3 gC(N_TOK / 128, HIDDEN / 128, BATCH);
    gemm_tf32<<<gC, dim3(256)>>>(w_out, ao_ptr, out, HIDDEN, b_out, 0, 0);
}

// round 10
// speedup vs baseline: 1.2742x; 1.2742x over previous
#include <cuda_runtime.h>
#include <cuda_fp16.h>
#include <cstdint>

#define N_TOK 2304
#define BATCH 4
#define HEADS 8
#define DHEAD 32
#define HIDDEN 256
#define QSCALE 0.17677669529663689f  // 32^-0.5

// ---- fp16 helpers ----
__device__ __forceinline__ uint32_t h2pk(float lo, float hi) {
    uint32_t r; asm("cvt.rn.f16x2.f32 %0,%1,%2;" : "=r"(r) : "f"(hi), "f"(lo)); return r;
}
__device__ __forceinline__ void mma_f16(float c[4], const uint32_t a[4],
                                        uint32_t b0, uint32_t b1) {
    asm("mma.sync.aligned.m16n8k16.row.col.f32.f16.f16.f32 "
        "{%0,%1,%2,%3},{%4,%5,%6,%7},{%8,%9},{%0,%1,%2,%3};"
        : "+f"(c[0]), "+f"(c[1]), "+f"(c[2]), "+f"(c[3])
        : "r"(a[0]), "r"(a[1]), "r"(a[2]), "r"(a[3]), "r"(b0), "r"(b1));
}
__device__ __forceinline__ void ldmx4t(uint32_t r[4], uint32_t addr) {
    asm volatile("ldmatrix.sync.aligned.m8n8.x4.trans.shared.b16 {%0,%1,%2,%3},[%4];"
                 : "=r"(r[0]), "=r"(r[1]), "=r"(r[2]), "=r"(r[3]) : "r"(addr));
}

// ---- cp.async helpers ----
__device__ __forceinline__ void cpa16(uint32_t smem_dst, const void* gsrc) {
    asm volatile("cp.async.cg.shared.global [%0],[%1],16;" :: "r"(smem_dst), "l"(gsrc));
}
__device__ __forceinline__ void cpa_commit() { asm volatile("cp.async.commit_group;"); }
__device__ __forceinline__ void cpa_wait1()  { asm volatile("cp.async.wait_group 1;"); }
__device__ __forceinline__ void cpa_wait0()  { asm volatile("cp.async.wait_group 0;"); }

// Scratch (alloc-free rule: __device__ globals)
__device__ __half g_qkvh[BATCH * 3 * HIDDEN * N_TOK];   // fp16 qkv
__device__ float  g_ao  [BATCH * HIDDEN * N_TOK];       // f32 attn out

// ---------------------------------------------------------------------------
// fp16 GEMM: Y[b][m][j] = sum_k W[m][k] * X[b][k][j], K=256.
// CTA 128m x 128j, 8 warps. X staged fp16 [k][j] pitch 136; B-frags via one
// ldmatrix.x4.trans per 8-j slab (covers full 32-k chunk); W A-frags from
// LDG.64 + pack, hoisted over the barrier. f32 accumulate.
// out_half=1 -> write __half (qkv path); else f32 (+bias).
// ---------------------------------------------------------------------------
#define HPG 136

__global__ __launch_bounds__(256)
void gemm_f16(const float* __restrict__ W, const float* __restrict__ X,
              void* __restrict__ Yv, int M,
              const float* __restrict__ bias, int qscale, int out_half)
{
    __shared__ __align__(16) uint16_t sX[32 * HPG];

    const int b  = blockIdx.z;
    const int m0 = blockIdx.y * 128;
    const int j0 = blockIdx.x * 128;
    const int tid = threadIdx.x;
    const int lane = tid & 31, warp = tid >> 5;
    const int g = lane >> 2, tg = lane & 3;
    const int mw = m0 + 16 * warp;

    const float* Xb = X + (size_t)b * 256 * N_TOK;
    const uint32_t xaddr0 = (uint32_t)__cvta_generic_to_shared(sX) + (uint32_t)lane * (HPG * 2);

    int skk[4], sj4[4];
#pragma unroll
    for (int l = 0; l < 4; l++) {
        int t = tid + l * 256;
        skk[l] = t >> 5; sj4[l] = (t & 31) << 2;
    }

    float acc[16][4];
#pragma unroll
    for (int nt = 0; nt < 16; nt++)
#pragma unroll
        for (int c = 0; c < 4; c++) acc[nt][c] = 0.f;

    for (int c = 0; c < 8; c++) {
        const int k0 = c * 32;
        if (c > 0) __syncthreads();   // previous chunk's reads complete

        // stage X chunk [32k][128j] as fp16
#pragma unroll
        for (int l = 0; l < 4; l++) {
            float4 xv = *(const float4*)(Xb + (size_t)(k0 + skk[l]) * N_TOK + j0 + sj4[l]);
            *(uint2*)&sX[skk[l] * HPG + sj4[l]] =
                make_uint2(h2pk(xv.x, xv.y), h2pk(xv.z, xv.w));
        }

        // W A-fragments (independent of smem -> overlap the barrier)
        uint32_t a[2][4];
#pragma unroll
        for (int kc = 0; kc < 2; kc++) {
            const float* wr = W + (size_t)(mw + g) * 256 + k0 + kc * 16;
            float2 w00 = *(const float2*)(wr + 2 * tg);
            float2 w10 = *(const float2*)(wr + 8 * 256 + 2 * tg);
            float2 w01 = *(const float2*)(wr + 2 * tg + 8);
            float2 w11 = *(const float2*)(wr + 8 * 256 + 2 * tg + 8);
            a[kc][0] = h2pk(w00.x, w00.y);
            a[kc][1] = h2pk(w10.x, w10.y);
            a[kc][2] = h2pk(w01.x, w01.y);
            a[kc][3] = h2pk(w11.x, w11.y);
        }
        __syncthreads();

#pragma unroll
        for (int nt = 0; nt < 16; nt++) {
            uint32_t kf[4];
            ldmx4t(kf, xaddr0 + (uint32_t)nt * 16);
            mma_f16(acc[nt], a[0], kf[0], kf[1]);
            mma_f16(acc[nt], a[1], kf[2], kf[3]);
        }
    }

    const int mr0 = mw + g, mr1 = mw + g + 8;
    const float s0 = (qscale && mr0 < HIDDEN) ? QSCALE : 1.f;
    const float s1 = (qscale && mr1 < HIDDEN) ? QSCALE : 1.f;
    if (out_half) {
        __half* Yh = (__half*)Yv;
        __half* y0 = Yh + ((size_t)b * M + mr0) * N_TOK + j0 + 2 * tg;
        __half* y1 = Yh + ((size_t)b * M + mr1) * N_TOK + j0 + 2 * tg;
#pragma unroll
        for (int nt = 0; nt < 16; nt++) {
            *(uint32_t*)(y0 + nt * 8) = h2pk(acc[nt][0] * s0, acc[nt][1] * s0);
            *(uint32_t*)(y1 + nt * 8) = h2pk(acc[nt][2] * s1, acc[nt][3] * s1);
        }
    } else {
        float* Yf = (float*)Yv;
        const float bv0 = bias ? bias[mr0] : 0.f;
        const float bv1 = bias ? bias[mr1] : 0.f;
        float* y0 = Yf + ((size_t)b * M + mr0) * N_TOK + j0 + 2 * tg;
        float* y1 = Yf + ((size_t)b * M + mr1) * N_TOK + j0 + 2 * tg;
#pragma unroll
        for (int nt = 0; nt < 16; nt++) {
            float2 o0 = { fmaf(acc[nt][0], s0, bv0), fmaf(acc[nt][1], s0, bv0) };
            float2 o1 = { fmaf(acc[nt][2], s1, bv1), fmaf(acc[nt][3], s1, bv1) };
            *(float2*)(y0 + nt * 8) = o0;
            *(float2*)(y1 + nt * 8) = o1;
        }
    }
}

// ---------------------------------------------------------------------------
// Batch-fused flash attention (R8-proven version, reverted verbatim):
// fp16 mma, max-free softmax, K/V single-buffer cp.async + pos_bias f32
// double-buffer cp.async prefetched one tile ahead.
// ---------------------------------------------------------------------------
#define HP 136                         // halves per d-row
#define KV_HALVES (2 * 32 * HP)        // per-batch K+V halves (8704)
#define KV_BYTES  (BATCH * KV_HALVES * 2)      // 69632
#define BIAS_PITCH 136                 // floats per bias row
#define BIAS_F (128 * BIAS_PITCH)      // floats per bias buffer (17408)
#define ATTN_SMEM (KV_BYTES + 2 * BIAS_F * 4)  // 208896 bytes
#define NTILES (N_TOK / 128)

__global__ __launch_bounds__(512, 1)
void attn_mma(const __half* __restrict__ qkvh, const float* __restrict__ posb,
              float* __restrict__ ao)
{
    extern __shared__ __align__(16) uint16_t sH[];
    float* sBias = (float*)((char*)sH + KV_BYTES);

    const int h = blockIdx.y, i0 = blockIdx.x * 128;
    const int tid  = threadIdx.x;
    const int lane = tid & 31, warp = tid >> 5;
    const int bb = warp & 3, mt = warp >> 2;
    const int g = lane >> 2, tg = lane & 3;

    const uint32_t smem_u32 = (uint32_t)__cvta_generic_to_shared(sH);
    const uint32_t bias_u32 = smem_u32 + KV_BYTES;

    uint16_t* sVh = sH + bb * KV_HALVES + 32 * HP;
    const uint32_t kaddr0 = smem_u32 + (uint32_t)bb * (KV_HALVES * 2) + (uint32_t)lane * (HP * 2);

    const uint16_t* qh = (const uint16_t*)(qkvh + ((size_t)bb * 3 * HIDDEN + h * DHEAD) * N_TOK);
    const float* pbase = posb + (size_t)h * N_TOK * N_TOK;

    const int gi0 = i0 + 32 * mt + g;

    // Q A-fragments fp16, held all kernel
    uint32_t qa[2][2][4];
#pragma unroll
    for (int rt = 0; rt < 2; rt++) {
        const int gi = gi0 + 16 * rt;
#pragma unroll
        for (int kc = 0; kc < 2; kc++) {
            int d0 = kc * 16 + 2 * tg;
#pragma unroll
            for (int q = 0; q < 4; q++) {
                int dd = d0 + (q >> 1) * 8;
                int ii = gi + (q & 1) * 8;
                qa[rt][kc][q] = (uint32_t)qh[(size_t)dd * N_TOK + ii]
                              | ((uint32_t)qh[(size_t)(dd + 1) * N_TOK + ii] << 16);
            }
        }
    }

    float o[2][4][4];
#pragma unroll
    for (int rt = 0; rt < 2; rt++)
#pragma unroll
        for (int dn = 0; dn < 4; dn++)
#pragma unroll
            for (int c = 0; c < 4; c++) o[rt][dn][c] = 0.f;
    float lp[2][4] = {{0.f,0.f,0.f,0.f},{0.f,0.f,0.f,0.f}};

    // ---- prologue: prefetch bias tile 0 into buffer 0 ----
#pragma unroll
    for (int t = tid; t < 4096; t += 512) {
        int row = t >> 5, ch = t & 31;
        cpa16(bias_u32 + (uint32_t)(row * BIAS_PITCH + ch * 4) * 4,
              pbase + (size_t)(i0 + row) * N_TOK + ch * 4);
    }
    cpa_commit();

    for (int jt = 0; jt < NTILES; jt++) {
        const int j0 = jt * 128;

        __syncthreads();   // previous tile's smem reads complete before overwrite

        // stage K/V (fp16, direct async copy, no conversion)
#pragma unroll
        for (int t = tid; t < 4096; t += 512) {
            int isv = t >> 11;
            int t2 = t & 2047;
            int bbs = t2 >> 9;
            int r = t2 & 511;
            int d = r >> 4, ch = r & 15;
            const __half* src = qkvh
                + ((size_t)(bbs * 3 * HIDDEN + (1 + isv) * HIDDEN + h * DHEAD + d)) * N_TOK
                + j0 + ch * 8;
            uint32_t dst = smem_u32
                + (uint32_t)(bbs * KV_HALVES + isv * 32 * HP + d * HP + ch * 8) * 2;
            cpa16(dst, src);
        }
        cpa_commit();

        if (jt + 1 < NTILES) {   // prefetch next bias tile into other buffer
            const int jn = (jt + 1) * 128;
            const uint32_t bdst = bias_u32 + (uint32_t)((jt + 1) & 1) * (BIAS_F * 4);
#pragma unroll
            for (int t = tid; t < 4096; t += 512) {
                int row = t >> 5, ch = t & 31;
                cpa16(bdst + (uint32_t)(row * BIAS_PITCH + ch * 4) * 4,
                      pbase + (size_t)(i0 + row) * N_TOK + jn + ch * 4);
            }
            cpa_commit();
            cpa_wait1();   // K/V_t + bias_t done; bias_{t+1} in flight
        } else {
            cpa_wait0();
        }
        __syncthreads();

        const float* sB = sBias + (jt & 1) * BIAS_F;

#pragma unroll
        for (int ntp = 0; ntp < 8; ntp++) {
            uint32_t pa[2][4];
#pragma unroll
            for (int half = 0; half < 2; half++) {
                const int nt = 2 * ntp + half;
                uint32_t kf[4];
                ldmx4t(kf, kaddr0 + (uint32_t)nt * 16);
#pragma unroll
                for (int rt = 0; rt < 2; rt++) {
                    const int row0 = 32 * mt + 16 * rt + g;
                    float2 x0 = *(const float2*)&sB[row0 * BIAS_PITCH + nt * 8 + 2 * tg];
                    float2 x1 = *(const float2*)&sB[(row0 + 8) * BIAS_PITCH + nt * 8 + 2 * tg];
                    float c[4] = { x0.x, x0.y, x1.x, x1.y };
                    mma_f16(c, qa[rt][0], kf[0], kf[1]);
                    mma_f16(c, qa[rt][1], kf[2], kf[3]);
                    float e0 = __expf(c[0]), e1 = __expf(c[1]);
                    float e2 = __expf(c[2]), e3 = __expf(c[3]);
                    lp[rt][0] += e0; lp[rt][1] += e1; lp[rt][2] += e2; lp[rt][3] += e3;
                    pa[rt][2 * half]     = h2pk(e0, e1);
                    pa[rt][2 * half + 1] = h2pk(e2, e3);
                }
            }
#pragma unroll
            for (int dn = 0; dn < 4; dn++) {
                uint32_t b0 = *(const uint32_t*)&sVh[(dn * 8 + g) * HP + ntp * 16 + 2 * tg];
                uint32_t b1 = *(const uint32_t*)&sVh[(dn * 8 + g) * HP + ntp * 16 + 8 + 2 * tg];
                mma_f16(o[0][dn], pa[0], b0, b1);
                mma_f16(o[1][dn], pa[1], b0, b1);
            }
        }
    }
    __syncthreads();

    // ---- epilogue: reduce l across quad lanes, normalize, stage, store ----
    float* sO = (float*)sH;   // [batch][128][33] f32 = 67584 B
#pragma unroll
    for (int rt = 0; rt < 2; rt++) {
        float l0 = lp[rt][0] + lp[rt][1];
        float l1 = lp[rt][2] + lp[rt][3];
        l0 += __shfl_xor_sync(0xffffffffu, l0, 1);
        l0 += __shfl_xor_sync(0xffffffffu, l0, 2);
        l1 += __shfl_xor_sync(0xffffffffu, l1, 1);
        l1 += __shfl_xor_sync(0xffffffffu, l1, 2);
        float inv0 = 1.f / l0, inv1 = 1.f / l1;
        int row0 = 32 * mt + 16 * rt + g;
        float* sOb = sO + bb * (128 * 33);
#pragma unroll
        for (int dn = 0; dn < 4; dn++) {
            int dcol = dn * 8 + 2 * tg;
            sOb[row0       * 33 + dcol]     = o[rt][dn][0] * inv0;
            sOb[row0       * 33 + dcol + 1] = o[rt][dn][1] * inv0;
            sOb[(row0 + 8) * 33 + dcol]     = o[rt][dn][2] * inv1;
            sOb[(row0 + 8) * 33 + dcol + 1] = o[rt][dn][3] * inv1;
        }
    }
    __syncthreads();
#pragma unroll
    for (int t = tid; t < 16384; t += 512) {
        int bbs = t >> 12, r = t & 4095;
        int d = r >> 7, ii = r & 127;
        ao[((size_t)bbs * HIDDEN + h * DHEAD + d) * N_TOK + i0 + ii] =
            sO[bbs * (128 * 33) + ii * 33 + d];
    }
}

// ---------------------------------------------------------------------------
extern "C" void kernel_launch(void* const* d_in, const int* in_sizes, int n_in,
                              void* d_out, int out_size)
{
    const float* x        = (const float*)d_in[0];
    const float* pos_bias = (const float*)d_in[1];
    const float* w_qkv    = (const float*)d_in[2];
    const float* w_out    = (const float*)d_in[3];
    const float* b_out    = (const float*)d_in[4];
    float* out = (float*)d_out;

    __half* qkvh_ptr; float* ao_ptr;
    cudaGetSymbolAddress((void**)&qkvh_ptr, g_qkvh);
    cudaGetSymbolAddress((void**)&ao_ptr,  g_ao);

    cudaFuncSetAttribute(attn_mma, cudaFuncAttributeMaxDynamicSharedMemorySize, ATTN_SMEM);

    dim3 gA(N_TOK / 128, (3 * HIDDEN) / 128, BATCH);
    gemm_f16<<<gA, dim3(256)>>>(w_qkv, x, qkvh_ptr, 3 * HIDDEN, nullptr, 1, 1);

    dim3 gB(N_TOK / 128, HEADS);
    attn_mma<<<gB, dim3(512), ATTN_SMEM>>>(qkvh_ptr, pos_bias, ao_ptr);

    dim3 gC(N_TOK / 128, HIDDEN / 128, BATCH);
    gemm_f16<<<gC, dim3(256)>>>(w_out, ao_ptr, out, HIDDEN, b_out, 0, 0);
}

// round 11
// speedup vs baseline: 1.5357x; 1.2052x over previous
#include <cuda_runtime.h>
#include <cuda_fp16.h>
#include <cstdint>

#define N_TOK 2304
#define BATCH 4
#define HEADS 8
#define DHEAD 32
#define HIDDEN 256
#define QSCALE 0.17677669529663689f  // 32^-0.5
#define LOG2E  1.4426950408889634f
#define ONES2  0x3C003C00u           // f16x2 (1.0, 1.0)

// ---- fp16 helpers ----
__device__ __forceinline__ uint32_t h2pk(float lo, float hi) {
    uint32_t r; asm("cvt.rn.f16x2.f32 %0,%1,%2;" : "=r"(r) : "f"(hi), "f"(lo)); return r;
}
__device__ __forceinline__ uint32_t ex2h2(uint32_t x) {
    uint32_t r; asm("ex2.approx.f16x2 %0,%1;" : "=r"(r) : "r"(x)); return r;
}
__device__ __forceinline__ void mma_f16(float c[4], const uint32_t a[4],
                                        uint32_t b0, uint32_t b1) {
    asm("mma.sync.aligned.m16n8k16.row.col.f32.f16.f16.f32 "
        "{%0,%1,%2,%3},{%4,%5,%6,%7},{%8,%9},{%0,%1,%2,%3};"
        : "+f"(c[0]), "+f"(c[1]), "+f"(c[2]), "+f"(c[3])
        : "r"(a[0]), "r"(a[1]), "r"(a[2]), "r"(a[3]), "r"(b0), "r"(b1));
}
__device__ __forceinline__ void ldmx4t(uint32_t r[4], uint32_t addr) {
    asm volatile("ldmatrix.sync.aligned.m8n8.x4.trans.shared.b16 {%0,%1,%2,%3},[%4];"
                 : "=r"(r[0]), "=r"(r[1]), "=r"(r[2]), "=r"(r[3]) : "r"(addr));
}

// ---- cp.async helpers ----
__device__ __forceinline__ void cpa16(uint32_t smem_dst, const void* gsrc) {
    asm volatile("cp.async.cg.shared.global [%0],[%1],16;" :: "r"(smem_dst), "l"(gsrc));
}
__device__ __forceinline__ void cpa_commit() { asm volatile("cp.async.commit_group;"); }
__device__ __forceinline__ void cpa_wait1()  { asm volatile("cp.async.wait_group 1;"); }
__device__ __forceinline__ void cpa_wait0()  { asm volatile("cp.async.wait_group 0;"); }

// Scratch (alloc-free rule: __device__ globals)
__device__ __half g_xh   [BATCH * 256 * N_TOK];          // fp16 x
__device__ __half g_wqkvh[3 * HIDDEN * 256];             // fp16 w_qkv
__device__ __half g_wouth[HIDDEN * 256];                 // fp16 w_out
__device__ __half g_qkvh [BATCH * 3 * HIDDEN * N_TOK];   // fp16 qkv
__device__ __half g_aoh  [BATCH * HIDDEN * N_TOK];       // fp16 attn out

// ---------------------------------------------------------------------------
// f32 -> f16 conversion for x, w_qkv, w_out (single launch)
// ---------------------------------------------------------------------------
__global__ __launch_bounds__(256)
void f2h3(const float* __restrict__ a0, __half* __restrict__ o0, int n0,
          const float* __restrict__ a1, __half* __restrict__ o1, int n1,
          const float* __restrict__ a2, __half* __restrict__ o2, int n2)
{
    int i = (blockIdx.x * 256 + threadIdx.x) * 4;
    const float* src; __half* dst;
    if (i < n0)            { src = a0 + i;           dst = o0 + i; }
    else if (i < n0 + n1)  { src = a1 + (i - n0);    dst = o1 + (i - n0); }
    else if (i < n0 + n1 + n2) { src = a2 + (i - n0 - n1); dst = o2 + (i - n0 - n1); }
    else return;
    float4 v = *(const float4*)src;
    *(uint2*)dst = make_uint2(h2pk(v.x, v.y), h2pk(v.z, v.w));
}

// ---------------------------------------------------------------------------
// all-fp16 GEMM: Y[b][m][j] = sum_k W[m][k]*X[b][k][j], K=256, f32 accum.
// X chunks staged via cp.async, double-buffered (prefetched 1 chunk ahead).
// qsc: scale applied to rows m<HIDDEN when out_half (q rows get QSCALE*LOG2E).
// ---------------------------------------------------------------------------
#define HPG 136

__global__ __launch_bounds__(256)
void gemm_h(const __half* __restrict__ W, const __half* __restrict__ X,
            void* __restrict__ Yv, int M,
            const float* __restrict__ bias, int qscale, int out_half)
{
    __shared__ __align__(16) uint16_t sX[2][32 * HPG];

    const int b  = blockIdx.z;
    const int m0 = blockIdx.y * 128;
    const int j0 = blockIdx.x * 128;
    const int tid = threadIdx.x;
    const int lane = tid & 31, warp = tid >> 5;
    const int g = lane >> 2, tg = lane & 3;
    const int mw = m0 + 16 * warp;

    const __half* Xb = X + (size_t)b * 256 * N_TOK;
    const uint32_t sbase = (uint32_t)__cvta_generic_to_shared(sX);

    int skk[2], sj8[2];
#pragma unroll
    for (int l = 0; l < 2; l++) {
        int t = tid + l * 256;
        skk[l] = t >> 4; sj8[l] = (t & 15) * 8;
    }

    float acc[16][4];
#pragma unroll
    for (int nt = 0; nt < 16; nt++)
#pragma unroll
        for (int c = 0; c < 4; c++) acc[nt][c] = 0.f;

    // prologue: issue chunk 0 into buffer 0
#pragma unroll
    for (int l = 0; l < 2; l++)
        cpa16(sbase + (uint32_t)(skk[l] * HPG + sj8[l]) * 2,
              Xb + (size_t)skk[l] * N_TOK + j0 + sj8[l]);
    cpa_commit();

    for (int c = 0; c < 8; c++) {
        const int k0 = c * 32;

        if (c > 0) __syncthreads();   // compute c-1 done before overwriting its buffer's twin
        if (c + 1 < 8) {
            const int kn = (c + 1) * 32;
            const uint32_t boff = (uint32_t)(((c + 1) & 1) * 32 * HPG) * 2;
#pragma unroll
            for (int l = 0; l < 2; l++)
                cpa16(sbase + boff + (uint32_t)(skk[l] * HPG + sj8[l]) * 2,
                      Xb + (size_t)(kn + skk[l]) * N_TOK + j0 + sj8[l]);
            cpa_commit();
        }

        // W A-fragments for chunk c (fp16 gmem, no smem dependence)
        uint32_t a[2][4];
#pragma unroll
        for (int kc = 0; kc < 2; kc++) {
            const __half* wr = W + (size_t)(mw + g) * 256 + k0 + kc * 16;
            a[kc][0] = *(const uint32_t*)(wr + 2 * tg);
            a[kc][1] = *(const uint32_t*)(wr + 8 * 256 + 2 * tg);
            a[kc][2] = *(const uint32_t*)(wr + 2 * tg + 8);
            a[kc][3] = *(const uint32_t*)(wr + 8 * 256 + 2 * tg + 8);
        }

        if (c + 1 < 8) cpa_wait1(); else cpa_wait0();
        __syncthreads();

        const uint32_t xaddr0 = sbase + (uint32_t)((c & 1) * 32 * HPG + lane * HPG) * 2;
#pragma unroll
        for (int nt = 0; nt < 16; nt++) {
            uint32_t kf[4];
            ldmx4t(kf, xaddr0 + (uint32_t)nt * 16);
            mma_f16(acc[nt], a[0], kf[0], kf[1]);
            mma_f16(acc[nt], a[1], kf[2], kf[3]);
        }
    }

    const int mr0 = mw + g, mr1 = mw + g + 8;
    if (out_half) {
        const float qs = QSCALE * LOG2E;   // fold log2e into q for ex2-softmax
        const float s0 = (qscale && mr0 < HIDDEN) ? qs : 1.f;
        const float s1 = (qscale && mr1 < HIDDEN) ? qs : 1.f;
        __half* Yh = (__half*)Yv;
        __half* y0 = Yh + ((size_t)b * M + mr0) * N_TOK + j0 + 2 * tg;
        __half* y1 = Yh + ((size_t)b * M + mr1) * N_TOK + j0 + 2 * tg;
#pragma unroll
        for (int nt = 0; nt < 16; nt++) {
            *(uint32_t*)(y0 + nt * 8) = h2pk(acc[nt][0] * s0, acc[nt][1] * s0);
            *(uint32_t*)(y1 + nt * 8) = h2pk(acc[nt][2] * s1, acc[nt][3] * s1);
        }
    } else {
        float* Yf = (float*)Yv;
        const float bv0 = bias ? bias[mr0] : 0.f;
        const float bv1 = bias ? bias[mr1] : 0.f;
        float* y0 = Yf + ((size_t)b * M + mr0) * N_TOK + j0 + 2 * tg;
        float* y1 = Yf + ((size_t)b * M + mr1) * N_TOK + j0 + 2 * tg;
#pragma unroll
        for (int nt = 0; nt < 16; nt++) {
            float2 o0 = { acc[nt][0] + bv0, acc[nt][1] + bv0 };
            float2 o1 = { acc[nt][2] + bv1, acc[nt][3] + bv1 };
            *(float2*)(y0 + nt * 8) = o0;
            *(float2*)(y1 + nt * 8) = o1;
        }
    }
}

// ---------------------------------------------------------------------------
// Batch-fused flash attention, fp16 mma, base-2 softmax via ex2.approx.f16x2.
// q pre-scaled by QSCALE*log2e; bias scaled by log2e at c-init; row sums l
// computed by a P x ones-mma (f32 accum) -> no shuffles, consistent P.
// K/V single-buffer cp.async + pos_bias f32 double-buffer cp.async (R8 flow).
// ---------------------------------------------------------------------------
#define HP 136
#define KV_HALVES (2 * 32 * HP)
#define KV_BYTES  (BATCH * KV_HALVES * 2)
#define BIAS_PITCH 136
#define BIAS_F (128 * BIAS_PITCH)
#define ATTN_SMEM (KV_BYTES + 2 * BIAS_F * 4)
#define NTILES (N_TOK / 128)

__global__ __launch_bounds__(512, 1)
void attn_mma(const __half* __restrict__ qkvh, const float* __restrict__ posb,
              __half* __restrict__ aoh)
{
    extern __shared__ __align__(16) uint16_t sH[];
    float* sBias = (float*)((char*)sH + KV_BYTES);

    const int h = blockIdx.y, i0 = blockIdx.x * 128;
    const int tid  = threadIdx.x;
    const int lane = tid & 31, warp = tid >> 5;
    const int bb = warp & 3, mt = warp >> 2;
    const int g = lane >> 2, tg = lane & 3;

    const uint32_t smem_u32 = (uint32_t)__cvta_generic_to_shared(sH);
    const uint32_t bias_u32 = smem_u32 + KV_BYTES;

    uint16_t* sVh = sH + bb * KV_HALVES + 32 * HP;
    const uint32_t kaddr0 = smem_u32 + (uint32_t)bb * (KV_HALVES * 2) + (uint32_t)lane * (HP * 2);

    const uint16_t* qh = (const uint16_t*)(qkvh + ((size_t)bb * 3 * HIDDEN + h * DHEAD) * N_TOK);
    const float* pbase = posb + (size_t)h * N_TOK * N_TOK;

    const int gi0 = i0 + 32 * mt + g;

    // Q A-fragments (q already scaled by QSCALE*log2e in gmem)
    uint32_t qa[2][2][4];
#pragma unroll
    for (int rt = 0; rt < 2; rt++) {
        const int gi = gi0 + 16 * rt;
#pragma unroll
        for (int kc = 0; kc < 2; kc++) {
            int d0 = kc * 16 + 2 * tg;
#pragma unroll
            for (int q = 0; q < 4; q++) {
                int dd = d0 + (q >> 1) * 8;
                int ii = gi + (q & 1) * 8;
                qa[rt][kc][q] = (uint32_t)qh[(size_t)dd * N_TOK + ii]
                              | ((uint32_t)qh[(size_t)(dd + 1) * N_TOK + ii] << 16);
            }
        }
    }

    float o[2][4][4];
#pragma unroll
    for (int rt = 0; rt < 2; rt++)
#pragma unroll
        for (int dn = 0; dn < 4; dn++)
#pragma unroll
            for (int c = 0; c < 4; c++) o[rt][dn][c] = 0.f;
    float ls[2][4];
#pragma unroll
    for (int rt = 0; rt < 2; rt++)
#pragma unroll
        for (int c = 0; c < 4; c++) ls[rt][c] = 0.f;

    // ---- prologue: prefetch bias tile 0 into buffer 0 ----
#pragma unroll
    for (int t = tid; t < 4096; t += 512) {
        int row = t >> 5, ch = t & 31;
        cpa16(bias_u32 + (uint32_t)(row * BIAS_PITCH + ch * 4) * 4,
              pbase + (size_t)(i0 + row) * N_TOK + ch * 4);
    }
    cpa_commit();

    for (int jt = 0; jt < NTILES; jt++) {
        const int j0 = jt * 128;

        __syncthreads();

        // stage K/V (fp16, direct async copy)
#pragma unroll
        for (int t = tid; t < 4096; t += 512) {
            int isv = t >> 11;
            int t2 = t & 2047;
            int bbs = t2 >> 9;
            int r = t2 & 511;
            int d = r >> 4, ch = r & 15;
            const __half* src = qkvh
                + ((size_t)(bbs * 3 * HIDDEN + (1 + isv) * HIDDEN + h * DHEAD + d)) * N_TOK
                + j0 + ch * 8;
            uint32_t dst = smem_u32
                + (uint32_t)(bbs * KV_HALVES + isv * 32 * HP + d * HP + ch * 8) * 2;
            cpa16(dst, src);
        }
        cpa_commit();

        if (jt + 1 < NTILES) {
            const int jn = (jt + 1) * 128;
            const uint32_t bdst = bias_u32 + (uint32_t)((jt + 1) & 1) * (BIAS_F * 4);
#pragma unroll
            for (int t = tid; t < 4096; t += 512) {
                int row = t >> 5, ch = t & 31;
                cpa16(bdst + (uint32_t)(row * BIAS_PITCH + ch * 4) * 4,
                      pbase + (size_t)(i0 + row) * N_TOK + jn + ch * 4);
            }
            cpa_commit();
            cpa_wait1();
        } else {
            cpa_wait0();
        }
        __syncthreads();

        const float* sB = sBias + (jt & 1) * BIAS_F;

#pragma unroll
        for (int ntp = 0; ntp < 8; ntp++) {
            uint32_t pa[2][4];
#pragma unroll
            for (int half = 0; half < 2; half++) {
                const int nt = 2 * ntp + half;
                uint32_t kf[4];
                ldmx4t(kf, kaddr0 + (uint32_t)nt * 16);
#pragma unroll
                for (int rt = 0; rt < 2; rt++) {
                    const int row0 = 32 * mt + 16 * rt + g;
                    float2 x0 = *(const float2*)&sB[row0 * BIAS_PITCH + nt * 8 + 2 * tg];
                    float2 x1 = *(const float2*)&sB[(row0 + 8) * BIAS_PITCH + nt * 8 + 2 * tg];
                    float c[4] = { x0.x * LOG2E, x0.y * LOG2E, x1.x * LOG2E, x1.y * LOG2E };
                    mma_f16(c, qa[rt][0], kf[0], kf[1]);
                    mma_f16(c, qa[rt][1], kf[2], kf[3]);
                    // P = 2^c, two exps per instruction, packed straight into A-frag
                    pa[rt][2 * half]     = ex2h2(h2pk(c[0], c[1]));
                    pa[rt][2 * half + 1] = ex2h2(h2pk(c[2], c[3]));
                }
            }
#pragma unroll
            for (int dn = 0; dn < 4; dn++) {
                uint32_t b0 = *(const uint32_t*)&sVh[(dn * 8 + g) * HP + ntp * 16 + 2 * tg];
                uint32_t b1 = *(const uint32_t*)&sVh[(dn * 8 + g) * HP + ntp * 16 + 8 + 2 * tg];
                mma_f16(o[0][dn], pa[0], b0, b1);
                mma_f16(o[1][dn], pa[1], b0, b1);
            }
            // row sums: l += P * ones (cross-lane reduction done by the mma)
            mma_f16(ls[0], pa[0], ONES2, ONES2);
            mma_f16(ls[1], pa[1], ONES2, ONES2);
        }
    }
    __syncthreads();

    // ---- epilogue: normalize (l from ones-mma), stage, store fp16 ----
    float* sO = (float*)sH;   // [batch][128][33] f32 = 67584 B
#pragma unroll
    for (int rt = 0; rt < 2; rt++) {
        float inv0 = 1.f / ls[rt][0];
        float inv1 = 1.f / ls[rt][2];
        int row0 = 32 * mt + 16 * rt + g;
        float* sOb = sO + bb * (128 * 33);
#pragma unroll
        for (int dn = 0; dn < 4; dn++) {
            int dcol = dn * 8 + 2 * tg;
            sOb[row0       * 33 + dcol]     = o[rt][dn][0] * inv0;
            sOb[row0       * 33 + dcol + 1] = o[rt][dn][1] * inv0;
            sOb[(row0 + 8) * 33 + dcol]     = o[rt][dn][2] * inv1;
            sOb[(row0 + 8) * 33 + dcol + 1] = o[rt][dn][3] * inv1;
        }
    }
    __syncthreads();
#pragma unroll
    for (int t = tid; t < 8192; t += 512) {
        int bbs = t >> 11, r = t & 2047;
        int d = r >> 6, ii2 = (r & 63) * 2;
        const float* s = sO + bbs * (128 * 33);
        uint32_t pk = h2pk(s[ii2 * 33 + d], s[(ii2 + 1) * 33 + d]);
        *(uint32_t*)&aoh[((size_t)bbs * HIDDEN + h * DHEAD + d) * N_TOK + i0 + ii2] = pk;
    }
}

// ---------------------------------------------------------------------------
extern "C" void kernel_launch(void* const* d_in, const int* in_sizes, int n_in,
                              void* d_out, int out_size)
{
    const float* x        = (const float*)d_in[0];
    const float* pos_bias = (const float*)d_in[1];
    const float* w_qkv    = (const float*)d_in[2];
    const float* w_out    = (const float*)d_in[3];
    const float* b_out    = (const float*)d_in[4];
    float* out = (float*)d_out;

    __half *xh, *wqkvh, *wouth, *qkvh, *aoh;
    cudaGetSymbolAddress((void**)&xh,    g_xh);
    cudaGetSymbolAddress((void**)&wqkvh, g_wqkvh);
    cudaGetSymbolAddress((void**)&wouth, g_wouth);
    cudaGetSymbolAddress((void**)&qkvh,  g_qkvh);
    cudaGetSymbolAddress((void**)&aoh,   g_aoh);

    cudaFuncSetAttribute(attn_mma, cudaFuncAttributeMaxDynamicSharedMemorySize, ATTN_SMEM);

    const int n0 = BATCH * 256 * N_TOK;        // 2359296
    const int n1 = 3 * HIDDEN * 256;           // 196608
    const int n2 = HIDDEN * 256;               // 65536
    const int tot4 = (n0 + n1 + n2) / 4;
    f2h3<<<(tot4 + 255) / 256, 256>>>(x, xh, n0, w_qkv, wqkvh, n1, w_out, wouth, n2);

    dim3 gA(N_TOK / 128, (3 * HIDDEN) / 128, BATCH);
    gemm_h<<<gA, dim3(256)>>>(wqkvh, xh, qkvh, 3 * HIDDEN, nullptr, 1, 1);

    dim3 gB(N_TOK / 128, HEADS);
    attn_mma<<<gB, dim3(512), ATTN_SMEM>>>(qkvh, pos_bias, aoh);

    dim3 gC(N_TOK / 128, HIDDEN / 128, BATCH);
    gemm_h<<<gC, dim3(256)>>>(wouth, aoh, out, HIDDEN, b_out, 0, 0);
}